// round 1
// baseline (speedup 1.0000x reference)
#include <cuda_runtime.h>

// Problem constants
#define T_SEQ   2048
#define N_BATCH 4
#define C_DIM   768
#define N_HEADS 12
#define H_DIM   64
#define M_ROWS  (N_BATCH * T_SEQ)   // 8192

// Scratch (static __device__ arrays: allocation-free per harness rules)
__device__ float g_qkv[(size_t)M_ROWS * 3 * C_DIM];   // [8192, 2304]  ~75.5 MB
__device__ float g_att[(size_t)M_ROWS * C_DIM];       // [8192, 768]   ~25 MB

// ---------------------------------------------------------------------------
// GEMM: C[M,N] = A[M,K] @ Bw[N,K]^T + bias[N]   (torch Linear convention)
// 128x128x8 tile, 256 threads, 8x8 micro-tile, register-staged prefetch.
// ---------------------------------------------------------------------------
__global__ __launch_bounds__(256, 2)
void sgemm_nt_bias(const float* __restrict__ A,
                   const float* __restrict__ Bw,
                   const float* __restrict__ bias,
                   float* __restrict__ C,
                   int Nd, int Kd)
{
    constexpr int BM = 128, BN = 128, BK = 8;
    __shared__ float As[BK][BM];   // transposed: [k][m]
    __shared__ float Bs[BK][BN];   // transposed: [k][n]

    const int tid = threadIdx.x;
    const int tx  = tid & 15;      // 0..15 -> 8 output cols each
    const int ty  = tid >> 4;      // 0..15 -> 8 output rows each
    const int bn  = blockIdx.x;
    const int bm  = blockIdx.y;

    const float* Ab = A  + (size_t)bm * BM * Kd;
    const float* Bb = Bw + (size_t)bn * BN * Kd;

    const int lr = tid >> 1;        // 0..127 tile row
    const int lc = (tid & 1) * 4;   // 0 or 4

    float4 av = *(const float4*)(Ab + (size_t)lr * Kd + lc);
    float4 bv = *(const float4*)(Bb + (size_t)lr * Kd + lc);

    float acc[8][8];
    #pragma unroll
    for (int i = 0; i < 8; i++)
        #pragma unroll
        for (int j = 0; j < 8; j++) acc[i][j] = 0.0f;

    const int nT = Kd / BK;
    for (int t = 0; t < nT; t++) {
        As[lc+0][lr] = av.x; As[lc+1][lr] = av.y;
        As[lc+2][lr] = av.z; As[lc+3][lr] = av.w;
        Bs[lc+0][lr] = bv.x; Bs[lc+1][lr] = bv.y;
        Bs[lc+2][lr] = bv.z; Bs[lc+3][lr] = bv.w;
        __syncthreads();

        if (t + 1 < nT) {   // prefetch next tile into registers
            av = *(const float4*)(Ab + (size_t)lr * Kd + (size_t)(t+1)*BK + lc);
            bv = *(const float4*)(Bb + (size_t)lr * Kd + (size_t)(t+1)*BK + lc);
        }

        #pragma unroll
        for (int k = 0; k < BK; k++) {
            float ar[8], br[8];
            *(float4*)&ar[0] = *(const float4*)&As[k][ty*8];
            *(float4*)&ar[4] = *(const float4*)&As[k][ty*8 + 4];
            *(float4*)&br[0] = *(const float4*)&Bs[k][tx*8];
            *(float4*)&br[4] = *(const float4*)&Bs[k][tx*8 + 4];
            #pragma unroll
            for (int i = 0; i < 8; i++)
                #pragma unroll
                for (int j = 0; j < 8; j++)
                    acc[i][j] = fmaf(ar[i], br[j], acc[i][j]);
        }
        __syncthreads();
    }

    const int row0 = bm*BM + ty*8;
    const int col0 = bn*BN + tx*8;
    float bz[8];
    *(float4*)&bz[0] = *(const float4*)(bias + col0);
    *(float4*)&bz[4] = *(const float4*)(bias + col0 + 4);
    #pragma unroll
    for (int i = 0; i < 8; i++) {
        float4 o0, o1;
        o0.x = acc[i][0] + bz[0]; o0.y = acc[i][1] + bz[1];
        o0.z = acc[i][2] + bz[2]; o0.w = acc[i][3] + bz[3];
        o1.x = acc[i][4] + bz[4]; o1.y = acc[i][5] + bz[5];
        o1.z = acc[i][6] + bz[6]; o1.w = acc[i][7] + bz[7];
        *(float4*)(C + (size_t)(row0+i)*Nd + col0)     = o0;
        *(float4*)(C + (size_t)(row0+i)*Nd + col0 + 4) = o1;
    }
}

// ---------------------------------------------------------------------------
// Flash attention, fp32. One block = (128 q-rows, one head, one batch).
// Online softmax over 32 KV tiles of 64 keys. Scale sqrt(64)=8 folded into Q.
// Thread micro-tile: 8 q-rows x 4 cols (cols = keys for S, head-dim for O).
// ---------------------------------------------------------------------------
#define QT_LD 132   // padded leading dim for [d][m] / [n][m] tiles (16B aligned rows)
#define KT_LD 68    // padded leading dim for [d][n] / [n][d] tiles

__global__ __launch_bounds__(256)
void attn_flash(const float* __restrict__ qkv, float* __restrict__ attout)
{
    extern __shared__ float sm[];
    float* Qt  = sm;                       // [64][132]  (d-major, pre-scaled by 8)
    float* Kt  = Qt  + 64*QT_LD;           // [64][68]   (d-major)
    float* Vs  = Kt  + 64*KT_LD;           // [64][68]   (n-major, natural)
    float* Pt  = Vs  + 64*KT_LD;           // [64][132]  (n-major: P^T)
    float* red = Pt  + 64*QT_LD;           // [128][17]
    float* m_s = red + 128*17;             // [128]
    float* l_s = m_s + 128;                // [128]
    float* scl = l_s + 128;                // [128]

    const int tid = threadIdx.x;
    const int tx  = tid & 15;   // 4 cols each
    const int ty  = tid >> 4;   // 8 rows each
    const int m0  = blockIdx.x * 128;
    const int h   = blockIdx.y;
    const int b   = blockIdx.z;

    const float* qb = qkv + (size_t)b * T_SEQ * (3*C_DIM) + h * H_DIM;
    const float* kb = qb + C_DIM;
    const float* vb = qb + 2*C_DIM;

    // Load Q tile [128 x 64], transposed into Qt[d][m], pre-scale by 8
    for (int idx = tid; idx < 128*64; idx += 256) {
        int d = idx & 63, r = idx >> 6;
        Qt[d*QT_LD + r] = qb[(size_t)(m0 + r)*(3*C_DIM) + d] * 8.0f;
    }
    if (tid < 128) { m_s[tid] = -1e30f; l_s[tid] = 0.0f; }

    float o[8][4];
    #pragma unroll
    for (int i = 0; i < 8; i++)
        #pragma unroll
        for (int j = 0; j < 4; j++) o[i][j] = 0.0f;
    __syncthreads();

    for (int kt = 0; kt < T_SEQ/64; kt++) {
        const int n0 = kt * 64;
        // K tile transposed [d][n]; V tile natural [n][d]
        for (int idx = tid; idx < 64*64; idx += 256) {
            int d = idx & 63, r = idx >> 6;
            Kt[d*KT_LD + r] = kb[(size_t)(n0 + r)*(3*C_DIM) + d];
        }
        for (int idx = tid; idx < 64*64; idx += 256) {
            int d = idx & 63, r = idx >> 6;
            Vs[r*KT_LD + d] = vb[(size_t)(n0 + r)*(3*C_DIM) + d];
        }
        __syncthreads();

        // S = (8*Q) K^T  -> s[8][4] per thread
        float s[8][4];
        #pragma unroll
        for (int i = 0; i < 8; i++)
            #pragma unroll
            for (int j = 0; j < 4; j++) s[i][j] = 0.0f;
        #pragma unroll 8
        for (int d = 0; d < 64; d++) {
            float qr[8], kr[4];
            *(float4*)&qr[0] = *(const float4*)&Qt[d*QT_LD + ty*8];
            *(float4*)&qr[4] = *(const float4*)&Qt[d*QT_LD + ty*8 + 4];
            *(float4*)&kr[0] = *(const float4*)&Kt[d*KT_LD + tx*4];
            #pragma unroll
            for (int i = 0; i < 8; i++)
                #pragma unroll
                for (int j = 0; j < 4; j++)
                    s[i][j] = fmaf(qr[i], kr[j], s[i][j]);
        }

        // per-thread row maxes -> smem reduction
        #pragma unroll
        for (int i = 0; i < 8; i++) {
            float rm = fmaxf(fmaxf(s[i][0], s[i][1]), fmaxf(s[i][2], s[i][3]));
            red[(ty*8 + i)*17 + tx] = rm;
        }
        __syncthreads();
        if (tid < 128) {
            float mo = m_s[tid];
            float mx = red[tid*17];
            #pragma unroll
            for (int t2 = 1; t2 < 16; t2++) mx = fmaxf(mx, red[tid*17 + t2]);
            float mn = fmaxf(mo, mx);
            m_s[tid] = mn;
            scl[tid] = __expf(mo - mn);
        }
        __syncthreads();

        // P = exp(S - m_new), store P^T, partial row-sums, rescale O
        #pragma unroll
        for (int i = 0; i < 8; i++) {
            const int row = ty*8 + i;
            const float mn = m_s[row];
            const float sc = scl[row];
            float rs = 0.0f;
            #pragma unroll
            for (int j = 0; j < 4; j++) {
                float p = __expf(s[i][j] - mn);
                rs += p;
                Pt[(tx*4 + j)*QT_LD + row] = p;
            }
            red[row*17 + tx] = rs;
            #pragma unroll
            for (int j = 0; j < 4; j++) o[i][j] *= sc;
        }
        __syncthreads();
        if (tid < 128) {
            float rs = 0.0f;
            #pragma unroll
            for (int t2 = 0; t2 < 16; t2++) rs += red[tid*17 + t2];
            l_s[tid] = l_s[tid]*scl[tid] + rs;
        }

        // O += P V
        #pragma unroll 8
        for (int n = 0; n < 64; n++) {
            float pr[8], vr[4];
            *(float4*)&pr[0] = *(const float4*)&Pt[n*QT_LD + ty*8];
            *(float4*)&pr[4] = *(const float4*)&Pt[n*QT_LD + ty*8 + 4];
            *(float4*)&vr[0] = *(const float4*)&Vs[n*KT_LD + tx*4];
            #pragma unroll
            for (int i = 0; i < 8; i++)
                #pragma unroll
                for (int j = 0; j < 4; j++)
                    o[i][j] = fmaf(pr[i], vr[j], o[i][j]);
        }
        __syncthreads();   // protects Kt/Vs/Pt/red/l_s for next iteration
    }

    // epilogue: O / l, write [b, t, h*64 + d] layout for the proj GEMM
    #pragma unroll
    for (int i = 0; i < 8; i++) {
        const int row = ty*8 + i;
        const float inv = 1.0f / l_s[row];
        float4 v;
        v.x = o[i][0]*inv; v.y = o[i][1]*inv; v.z = o[i][2]*inv; v.w = o[i][3]*inv;
        *(float4*)(attout + (size_t)(b*T_SEQ + m0 + row)*C_DIM + h*H_DIM + tx*4) = v;
    }
}

// ---------------------------------------------------------------------------
extern "C" void kernel_launch(void* const* d_in, const int* in_sizes, int n_in,
                              void* d_out, int out_size)
{
    (void)in_sizes; (void)n_in; (void)out_size;
    const float* x      = (const float*)d_in[0];
    const float* qkv_w  = (const float*)d_in[1];
    const float* qkv_b  = (const float*)d_in[2];
    const float* proj_w = (const float*)d_in[3];
    const float* proj_b = (const float*)d_in[4];
    float* out = (float*)d_out;

    float *qkv_ptr, *att_ptr;
    cudaGetSymbolAddress((void**)&qkv_ptr, g_qkv);
    cudaGetSymbolAddress((void**)&att_ptr, g_att);

    constexpr size_t ATTN_SMEM =
        (size_t)(64*QT_LD + 64*KT_LD + 64*KT_LD + 64*QT_LD + 128*17 + 3*128) * sizeof(float); // 112640 B
    cudaFuncSetAttribute(attn_flash, cudaFuncAttributeMaxDynamicSharedMemorySize, (int)ATTN_SMEM);

    // 1) QKV GEMM: [8192,768] x [2304,768]^T + b -> g_qkv
    sgemm_nt_bias<<<dim3(3*C_DIM/128, M_ROWS/128), 256>>>(x, qkv_w, qkv_b, qkv_ptr, 3*C_DIM, C_DIM);
    // 2) flash attention -> g_att ([B,T,C])
    attn_flash<<<dim3(T_SEQ/128, N_HEADS, N_BATCH), 256, ATTN_SMEM>>>(qkv_ptr, att_ptr);
    // 3) proj GEMM: [8192,768] x [768,768]^T + b -> out
    sgemm_nt_bias<<<dim3(C_DIM/128, M_ROWS/128), 256>>>(att_ptr, proj_w, proj_b, out, C_DIM, C_DIM);
}

// round 3
// speedup vs baseline: 1.2141x; 1.2141x over previous
#include <cuda_runtime.h>
#include <cuda_bf16.h>
#include <cstdint>

// Problem constants
#define T_SEQ   2048
#define N_BATCH 4
#define C_DIM   768
#define N_HEADS 12
#define H_DIM   64
#define M_ROWS  (N_BATCH * T_SEQ)   // 8192

// Scratch (static __device__ arrays: allocation-free per harness rules)
__device__ float g_qkv[(size_t)M_ROWS * 3 * C_DIM];   // [8192, 2304]
__device__ float g_att[(size_t)M_ROWS * C_DIM];       // [8192, 768]

// ===========================================================================
// mma.sync helpers (sm_80-class ISA, valid at plain sm_100 PTX target)
// ===========================================================================
__device__ __forceinline__ uint32_t smem_u32(const void* p) {
    uint32_t a;
    asm("{ .reg .u64 t; cvta.to.shared.u64 t, %1; cvt.u32.u64 %0, t; }"
        : "=r"(a) : "l"(p));
    return a;
}

#define LDSM4(r, addr) \
    asm volatile("ldmatrix.sync.aligned.m8n8.x4.shared.b16 {%0,%1,%2,%3}, [%4];" \
                 : "=r"((r)[0]), "=r"((r)[1]), "=r"((r)[2]), "=r"((r)[3]) \
                 : "r"(addr))

#define MMA_BF16(c, a, b) \
    asm volatile("mma.sync.aligned.m16n8k16.row.col.f32.bf16.bf16.f32 " \
                 "{%0,%1,%2,%3}, {%4,%5,%6,%7}, {%8,%9}, {%0,%1,%2,%3};" \
                 : "+f"((c)[0]), "+f"((c)[1]), "+f"((c)[2]), "+f"((c)[3]) \
                 : "r"((a)[0]), "r"((a)[1]), "r"((a)[2]), "r"((a)[3]), \
                   "r"((b)[0]), "r"((b)[1]))

// Split two floats into packed bf16 hi/lo pairs (x in low half)
__device__ __forceinline__ void split2(float x, float y, uint32_t& hi, uint32_t& lo) {
    __nv_bfloat16 hx = __float2bfloat16_rn(x);
    __nv_bfloat16 hy = __float2bfloat16_rn(y);
    float lx = x - __bfloat162float(hx);
    float ly = y - __bfloat162float(hy);
    __nv_bfloat16 lxh = __float2bfloat16_rn(lx);
    __nv_bfloat16 lyh = __float2bfloat16_rn(ly);
    hi = (uint32_t)__bfloat16_as_ushort(hx) | ((uint32_t)__bfloat16_as_ushort(hy) << 16);
    lo = (uint32_t)__bfloat16_as_ushort(lxh) | ((uint32_t)__bfloat16_as_ushort(lyh) << 16);
}

// ===========================================================================
// bf16x3-split tensor-core GEMM:  C[M,N] = A[M,K] @ W[N,K]^T + bias[N]
// Block 128x128, BK=32, 8 warps (warp tile 64x32), fp32 accum in registers.
// Smem rows padded to 40 halves -> conflict-free ldmatrix.
// ===========================================================================
#define SROW 40   // halves per smem row (32 data + 8 pad)

__global__ __launch_bounds__(256, 1)
void gemm_bf16x3(const float* __restrict__ A,
                 const float* __restrict__ W,
                 const float* __restrict__ bias,
                 float* __restrict__ C,
                 int Nd, int Kd)
{
    __shared__ __align__(16) uint32_t sAhi[128 * SROW / 2];
    __shared__ __align__(16) uint32_t sAlo[128 * SROW / 2];
    __shared__ __align__(16) uint32_t sBhi[128 * SROW / 2];
    __shared__ __align__(16) uint32_t sBlo[128 * SROW / 2];

    const int tid  = threadIdx.x;
    const int lane = tid & 31;
    const int wid  = tid >> 5;
    const int wm   = wid & 1;    // warp row (2)
    const int wn   = wid >> 1;   // warp col (4)
    const int bn = blockIdx.x, bm = blockIdx.y;

    // -------- producer mapping: thread -> (row, 4-col base) --------
    const int lr = tid >> 1;
    const int cb = (tid & 1) * 4;
    const float* ga = A + (size_t)(bm * 128 + lr) * Kd + cb;
    const float* gb = W + (size_t)(bn * 128 + lr) * Kd + cb;
    const int sIdx = lr * (SROW / 2) + (cb >> 1);   // u32 index

    float4 pa[4], pb[4];
    #pragma unroll
    for (int i = 0; i < 4; i++) {
        pa[i] = *(const float4*)(ga + i * 8);
        pb[i] = *(const float4*)(gb + i * 8);
    }

    float acc[4][4][4];
    #pragma unroll
    for (int mt = 0; mt < 4; mt++)
        #pragma unroll
        for (int nt = 0; nt < 4; nt++)
            #pragma unroll
            for (int q = 0; q < 4; q++) acc[mt][nt][q] = 0.0f;

    // -------- ldmatrix lane base addresses --------
    const uint32_t aOff = ((uint32_t)(wm * 64 + (lane & 15)) * SROW + (lane >> 4) * 8) * 2;
    const uint32_t bOff = ((uint32_t)(wn * 32 + ((lane >> 4) & 1) * 8 + (lane & 7)) * SROW
                          + ((lane >> 3) & 1) * 8) * 2;
    const uint32_t aHiB = smem_u32(sAhi) + aOff, aLoB = smem_u32(sAlo) + aOff;
    const uint32_t bHiB = smem_u32(sBhi) + bOff, bLoB = smem_u32(sBlo) + bOff;

    const int nch = Kd / 32;
    for (int c = 0; c < nch; c++) {
        // store prefetched chunk (split into hi/lo)
        #pragma unroll
        for (int i = 0; i < 4; i++) {
            uint32_t h0, l0, h1, l1;
            split2(pa[i].x, pa[i].y, h0, l0);
            split2(pa[i].z, pa[i].w, h1, l1);
            sAhi[sIdx + i * 4] = h0; sAhi[sIdx + i * 4 + 1] = h1;
            sAlo[sIdx + i * 4] = l0; sAlo[sIdx + i * 4 + 1] = l1;
            split2(pb[i].x, pb[i].y, h0, l0);
            split2(pb[i].z, pb[i].w, h1, l1);
            sBhi[sIdx + i * 4] = h0; sBhi[sIdx + i * 4 + 1] = h1;
            sBlo[sIdx + i * 4] = l0; sBlo[sIdx + i * 4 + 1] = l1;
        }
        __syncthreads();

        if (c + 1 < nch) {   // prefetch next chunk while computing
            #pragma unroll
            for (int i = 0; i < 4; i++) {
                pa[i] = *(const float4*)(ga + (size_t)(c + 1) * 32 + i * 8);
                pb[i] = *(const float4*)(gb + (size_t)(c + 1) * 32 + i * 8);
            }
        }

        #pragma unroll
        for (int ks = 0; ks < 2; ks++) {
            uint32_t ah[4][4], al[4][4], bh[4][2], bl[4][2];
            #pragma unroll
            for (int mt = 0; mt < 4; mt++) {
                const uint32_t ad = (uint32_t)(mt * 16 * SROW + ks * 16) * 2;
                LDSM4(ah[mt], aHiB + ad);
                LDSM4(al[mt], aLoB + ad);
            }
            #pragma unroll
            for (int p = 0; p < 2; p++) {
                const uint32_t bd = (uint32_t)(p * 16 * SROW + ks * 16) * 2;
                uint32_t r[4];
                LDSM4(r, bHiB + bd);
                bh[2*p][0] = r[0]; bh[2*p][1] = r[1];
                bh[2*p+1][0] = r[2]; bh[2*p+1][1] = r[3];
                LDSM4(r, bLoB + bd);
                bl[2*p][0] = r[0]; bl[2*p][1] = r[1];
                bl[2*p+1][0] = r[2]; bl[2*p+1][1] = r[3];
            }
            #pragma unroll
            for (int mt = 0; mt < 4; mt++)
                #pragma unroll
                for (int nt = 0; nt < 4; nt++) {
                    MMA_BF16(acc[mt][nt], ah[mt], bh[nt]);
                    MMA_BF16(acc[mt][nt], al[mt], bh[nt]);
                    MMA_BF16(acc[mt][nt], ah[mt], bl[nt]);
                }
        }
        __syncthreads();
    }

    // -------- epilogue: acc + bias -> C --------
    const int gid = lane >> 2, tig = lane & 3;
    const int row0 = bm * 128 + wm * 64;
    const int col0 = bn * 128 + wn * 32;
    #pragma unroll
    for (int mt = 0; mt < 4; mt++)
        #pragma unroll
        for (int nt = 0; nt < 4; nt++) {
            const int r  = row0 + mt * 16 + gid;
            const int cc = col0 + nt * 8 + tig * 2;
            const float2 bz = *(const float2*)(bias + cc);
            float2 o0, o1;
            o0.x = acc[mt][nt][0] + bz.x; o0.y = acc[mt][nt][1] + bz.y;
            o1.x = acc[mt][nt][2] + bz.x; o1.y = acc[mt][nt][3] + bz.y;
            *(float2*)(C + (size_t)r * Nd + cc)       = o0;
            *(float2*)(C + (size_t)(r + 8) * Nd + cc) = o1;
        }
}

// ===========================================================================
// Flash attention, fp32 SIMT (unchanged from verified baseline)
// ===========================================================================
#define QT_LD 132
#define KT_LD 68

__global__ __launch_bounds__(256)
void attn_flash(const float* __restrict__ qkv, float* __restrict__ attout)
{
    extern __shared__ float sm[];
    float* Qt  = sm;
    float* Kt  = Qt  + 64*QT_LD;
    float* Vs  = Kt  + 64*KT_LD;
    float* Pt  = Vs  + 64*KT_LD;
    float* red = Pt  + 64*QT_LD;
    float* m_s = red + 128*17;
    float* l_s = m_s + 128;
    float* scl = l_s + 128;

    const int tid = threadIdx.x;
    const int tx  = tid & 15;
    const int ty  = tid >> 4;
    const int m0  = blockIdx.x * 128;
    const int h   = blockIdx.y;
    const int b   = blockIdx.z;

    const float* qb = qkv + (size_t)b * T_SEQ * (3*C_DIM) + h * H_DIM;
    const float* kb = qb + C_DIM;
    const float* vb = qb + 2*C_DIM;

    for (int idx = tid; idx < 128*64; idx += 256) {
        int d = idx & 63, r = idx >> 6;
        Qt[d*QT_LD + r] = qb[(size_t)(m0 + r)*(3*C_DIM) + d] * 8.0f;
    }
    if (tid < 128) { m_s[tid] = -1e30f; l_s[tid] = 0.0f; }

    float o[8][4];
    #pragma unroll
    for (int i = 0; i < 8; i++)
        #pragma unroll
        for (int j = 0; j < 4; j++) o[i][j] = 0.0f;
    __syncthreads();

    for (int kt = 0; kt < T_SEQ/64; kt++) {
        const int n0 = kt * 64;
        for (int idx = tid; idx < 64*64; idx += 256) {
            int d = idx & 63, r = idx >> 6;
            Kt[d*KT_LD + r] = kb[(size_t)(n0 + r)*(3*C_DIM) + d];
        }
        for (int idx = tid; idx < 64*64; idx += 256) {
            int d = idx & 63, r = idx >> 6;
            Vs[r*KT_LD + d] = vb[(size_t)(n0 + r)*(3*C_DIM) + d];
        }
        __syncthreads();

        float s[8][4];
        #pragma unroll
        for (int i = 0; i < 8; i++)
            #pragma unroll
            for (int j = 0; j < 4; j++) s[i][j] = 0.0f;
        #pragma unroll 8
        for (int d = 0; d < 64; d++) {
            float qr[8], kr[4];
            *(float4*)&qr[0] = *(const float4*)&Qt[d*QT_LD + ty*8];
            *(float4*)&qr[4] = *(const float4*)&Qt[d*QT_LD + ty*8 + 4];
            *(float4*)&kr[0] = *(const float4*)&Kt[d*KT_LD + tx*4];
            #pragma unroll
            for (int i = 0; i < 8; i++)
                #pragma unroll
                for (int j = 0; j < 4; j++)
                    s[i][j] = fmaf(qr[i], kr[j], s[i][j]);
        }

        #pragma unroll
        for (int i = 0; i < 8; i++) {
            float rm = fmaxf(fmaxf(s[i][0], s[i][1]), fmaxf(s[i][2], s[i][3]));
            red[(ty*8 + i)*17 + tx] = rm;
        }
        __syncthreads();
        if (tid < 128) {
            float mo = m_s[tid];
            float mx = red[tid*17];
            #pragma unroll
            for (int t2 = 1; t2 < 16; t2++) mx = fmaxf(mx, red[tid*17 + t2]);
            float mn = fmaxf(mo, mx);
            m_s[tid] = mn;
            scl[tid] = __expf(mo - mn);
        }
        __syncthreads();

        #pragma unroll
        for (int i = 0; i < 8; i++) {
            const int row = ty*8 + i;
            const float mn = m_s[row];
            const float sc = scl[row];
            float rs = 0.0f;
            #pragma unroll
            for (int j = 0; j < 4; j++) {
                float p = __expf(s[i][j] - mn);
                rs += p;
                Pt[(tx*4 + j)*QT_LD + row] = p;
            }
            red[row*17 + tx] = rs;
            #pragma unroll
            for (int j = 0; j < 4; j++) o[i][j] *= sc;
        }
        __syncthreads();
        if (tid < 128) {
            float rs = 0.0f;
            #pragma unroll
            for (int t2 = 0; t2 < 16; t2++) rs += red[tid*17 + t2];
            l_s[tid] = l_s[tid]*scl[tid] + rs;
        }

        #pragma unroll 8
        for (int n = 0; n < 64; n++) {
            float pr[8], vr[4];
            *(float4*)&pr[0] = *(const float4*)&Pt[n*QT_LD + ty*8];
            *(float4*)&pr[4] = *(const float4*)&Pt[n*QT_LD + ty*8 + 4];
            *(float4*)&vr[0] = *(const float4*)&Vs[n*KT_LD + tx*4];
            #pragma unroll
            for (int i = 0; i < 8; i++)
                #pragma unroll
                for (int j = 0; j < 4; j++)
                    o[i][j] = fmaf(pr[i], vr[j], o[i][j]);
        }
        __syncthreads();
    }

    #pragma unroll
    for (int i = 0; i < 8; i++) {
        const int row = ty*8 + i;
        const float inv = 1.0f / l_s[row];
        float4 v;
        v.x = o[i][0]*inv; v.y = o[i][1]*inv; v.z = o[i][2]*inv; v.w = o[i][3]*inv;
        *(float4*)(attout + (size_t)(b*T_SEQ + m0 + row)*C_DIM + h*H_DIM + tx*4) = v;
    }
}

// ===========================================================================
extern "C" void kernel_launch(void* const* d_in, const int* in_sizes, int n_in,
                              void* d_out, int out_size)
{
    (void)in_sizes; (void)n_in; (void)out_size;
    const float* x      = (const float*)d_in[0];
    const float* qkv_w  = (const float*)d_in[1];
    const float* qkv_b  = (const float*)d_in[2];
    const float* proj_w = (const float*)d_in[3];
    const float* proj_b = (const float*)d_in[4];
    float* out = (float*)d_out;

    float *qkv_ptr, *att_ptr;
    cudaGetSymbolAddress((void**)&qkv_ptr, g_qkv);
    cudaGetSymbolAddress((void**)&att_ptr, g_att);

    constexpr size_t ATTN_SMEM =
        (size_t)(64*QT_LD + 64*KT_LD + 64*KT_LD + 64*QT_LD + 128*17 + 3*128) * sizeof(float);
    cudaFuncSetAttribute(attn_flash, cudaFuncAttributeMaxDynamicSharedMemorySize, (int)ATTN_SMEM);

    // 1) QKV GEMM: [8192,768] x [2304,768]^T + b -> g_qkv   (bf16x3 tensor)
    gemm_bf16x3<<<dim3(3*C_DIM/128, M_ROWS/128), 256>>>(x, qkv_w, qkv_b, qkv_ptr, 3*C_DIM, C_DIM);
    // 2) flash attention -> g_att
    attn_flash<<<dim3(T_SEQ/128, N_HEADS, N_BATCH), 256, ATTN_SMEM>>>(qkv_ptr, att_ptr);
    // 3) proj GEMM: [8192,768] x [768,768]^T + b -> out     (bf16x3 tensor)
    gemm_bf16x3<<<dim3(C_DIM/128, M_ROWS/128), 256>>>(att_ptr, proj_w, proj_b, out, C_DIM, C_DIM);
}